// round 1
// baseline (speedup 1.0000x reference)
#include <cuda_runtime.h>
#include <cstdint>

// libdevice precise expf (same function XLA lowers jnp.exp(f32) to),
// immune to --use_fast_math remapping of expf -> __expf.
extern "C" __device__ float __nv_expf(float);

// ---------------- problem constants ----------------
#define N_IMG 8
#define N_ANCH 250000
#define K_PRE 2000
#define K_POST 1000
#define CAND_CAP 4096
#define NMS_THRESH 0.7f
#define XFORM_CLIP 4.135166556742356f
#define XMAX 1332.0f
#define YMAX 799.0f
#define NEG_BIG -1e9f

// ---------------- device scratch (no allocs allowed) ----------------
__device__ unsigned int g_hist[N_IMG * 256];
__device__ unsigned int g_state[N_IMG * 4];        // [0]=prefix/T, [1]=krem, [2]=cand_cnt
__device__ unsigned long long g_cand[N_IMG * CAND_CAP];
__device__ int   g_topk_idx[N_IMG * K_PRE];
__device__ float g_props[N_IMG * K_PRE * 4];
__device__ float g_scores[N_IMG * K_PRE];
__device__ unsigned char g_valid[N_IMG * K_PRE];
__device__ unsigned long long g_mask[N_IMG * 2048 * 32];   // 4 MB suppression bitmask
__device__ unsigned char g_keep[N_IMG * K_PRE];

__device__ __forceinline__ unsigned int okey_of(float f) {
    unsigned int b = __float_as_uint(f);
    return b ^ ((b & 0x80000000u) ? 0xFFFFFFFFu : 0x80000000u);
}

// ---------------- init ----------------
__global__ void init_kernel() {
    int img = blockIdx.x, t = threadIdx.x;
    g_hist[img * 256 + t] = 0u;
    if (t == 0) {
        g_state[img * 4 + 0] = 0u;
        g_state[img * 4 + 1] = K_PRE;
        g_state[img * 4 + 2] = 0u;
    }
}

// ---------------- radix-select histogram pass ----------------
__global__ void hist_kernel(const float* __restrict__ obj, int pass) {
    int img = blockIdx.y;
    __shared__ unsigned int sh[8][256];
    int t = threadIdx.x, w = t >> 5;
    for (int i = t; i < 8 * 256; i += 256) ((unsigned int*)sh)[i] = 0u;
    __syncthreads();
    unsigned int prefix = g_state[img * 4 + 0];
    int dsh = 24 - 8 * pass;
    const float* o = obj + (size_t)img * N_ANCH;
    for (int i = blockIdx.x * 256 + t; i < N_ANCH; i += gridDim.x * 256) {
        unsigned int k = okey_of(o[i]);
        bool match = (pass == 0) || ((k >> (32 - 8 * pass)) == prefix);
        if (match) atomicAdd(&sh[w][(k >> dsh) & 255u], 1u);
    }
    __syncthreads();
    unsigned int s = 0;
    for (int ww = 0; ww < 8; ww++) s += sh[ww][t];
    if (s) atomicAdd(&g_hist[img * 256 + t], s);
}

// ---------------- digit scan (1 thread per image) ----------------
__global__ void scan_kernel() {
    int img = threadIdx.x;
    if (img >= N_IMG) return;
    unsigned int k = g_state[img * 4 + 1];
    unsigned int cum = 0, kk = k;
    int sel = 0;
    bool found = false;
    for (int d = 255; d >= 0; d--) {
        unsigned int c = g_hist[img * 256 + d];
        g_hist[img * 256 + d] = 0u;   // reset for next pass / next launch
        if (!found && cum + c >= k) { sel = d; kk = k - cum; found = true; }
        cum += c;
    }
    g_state[img * 4 + 0] = (g_state[img * 4 + 0] << 8) | (unsigned int)sel;
    g_state[img * 4 + 1] = kk;
}

// ---------------- compact candidates (okey >= T) ----------------
__global__ void compact_kernel(const float* __restrict__ obj) {
    int img = blockIdx.y;
    unsigned int T = g_state[img * 4 + 0];
    const float* o = obj + (size_t)img * N_ANCH;
    for (int i = blockIdx.x * 256 + threadIdx.x; i < N_ANCH; i += gridDim.x * 256) {
        unsigned int k = okey_of(o[i]);
        if (k >= T) {
            unsigned int pos = atomicAdd(&g_state[img * 4 + 2], 1u);
            if (pos < CAND_CAP)
                g_cand[img * CAND_CAP + pos] =
                    ((unsigned long long)k << 32) | (unsigned int)(~(unsigned int)i);
        }
    }
}

// ---------------- per-image bitonic sort (descending) + emit top-2000 ----------------
__global__ void sort_kernel() {
    int img = blockIdx.x, t = threadIdx.x;   // 1024 threads
    __shared__ unsigned long long sh[CAND_CAP];
    unsigned int cnt = g_state[img * 4 + 2];
    if (cnt > CAND_CAP) cnt = CAND_CAP;
    for (int i = t; i < CAND_CAP; i += 1024)
        sh[i] = (i < (int)cnt) ? g_cand[img * CAND_CAP + i] : 0ull;
    __syncthreads();
    for (int k = 2; k <= CAND_CAP; k <<= 1) {
        for (int j = k >> 1; j > 0; j >>= 1) {
            for (int i = t; i < CAND_CAP; i += 1024) {
                int ixj = i ^ j;
                if (ixj > i) {
                    bool desc = ((i & k) == 0);
                    unsigned long long A = sh[i], B = sh[ixj];
                    if (desc ? (A < B) : (A > B)) { sh[i] = B; sh[ixj] = A; }
                }
            }
            __syncthreads();
        }
    }
    for (int r = t; r < K_PRE; r += 1024)
        g_topk_idx[img * K_PRE + r] = (int)(~(unsigned int)(sh[r] & 0xFFFFFFFFull));
}

// ---------------- decode + clip + valid + score gather ----------------
__global__ void decode_kernel(const float* __restrict__ anchors,
                              const float* __restrict__ obj,
                              const float* __restrict__ deltas) {
    int img = blockIdx.y;
    int r = blockIdx.x * blockDim.x + threadIdx.x;
    if (r >= K_PRE) return;
    int idx = g_topk_idx[img * K_PRE + r];
    const float* A = anchors + (size_t)idx * 4;
    const float* D = deltas + ((size_t)img * N_ANCH + idx) * 4;
    float a0 = A[0], a1 = A[1], a2 = A[2], a3 = A[3];
    float w  = __fadd_rn(__fsub_rn(a2, a0), 1.0f);
    float h  = __fadd_rn(__fsub_rn(a3, a1), 1.0f);
    float cx = __fadd_rn(a0, __fmul_rn(0.5f, w));
    float cy = __fadd_rn(a1, __fmul_rn(0.5f, h));
    float dx = D[0], dy = D[1];
    float dw = fminf(D[2], XFORM_CLIP);
    float dh = fminf(D[3], XFORM_CLIP);
    float pcx = __fadd_rn(__fmul_rn(dx, w), cx);
    float pcy = __fadd_rn(__fmul_rn(dy, h), cy);
    float pw  = __fmul_rn(__nv_expf(dw), w);
    float ph  = __fmul_rn(__nv_expf(dh), h);
    float hx = __fmul_rn(0.5f, pw), hy = __fmul_rn(0.5f, ph);
    float x1 = __fsub_rn(pcx, hx);
    float y1 = __fsub_rn(pcy, hy);
    float x2 = __fsub_rn(__fadd_rn(pcx, hx), 1.0f);
    float y2 = __fsub_rn(__fadd_rn(pcy, hy), 1.0f);
    x1 = fminf(fmaxf(x1, 0.0f), XMAX);
    x2 = fminf(fmaxf(x2, 0.0f), XMAX);
    y1 = fminf(fmaxf(y1, 0.0f), YMAX);
    y2 = fminf(fmaxf(y2, 0.0f), YMAX);
    float* P = &g_props[(img * K_PRE + r) * 4];
    P[0] = x1; P[1] = y1; P[2] = x2; P[3] = y2;
    bool v = (__fadd_rn(__fsub_rn(x2, x1), 1.0f) >= 0.0f) &&
             (__fadd_rn(__fsub_rn(y2, y1), 1.0f) >= 0.0f);
    g_valid[img * K_PRE + r] = v ? 1 : 0;
    g_scores[img * K_PRE + r] = obj[(size_t)img * N_ANCH + idx];
}

// ---------------- 64x64 IoU bitmask ----------------
__global__ void mask_kernel() {
    int img = blockIdx.z, rb = blockIdx.y, cb = blockIdx.x;
    int t = threadIdx.x;   // 64 threads
    int row = rb * 64 + t;
    unsigned long long* Mrow = &g_mask[((size_t)img * 2048 + row) * 32];
    if (cb < rb) { Mrow[cb] = 0ull; return; }
    __shared__ float cbx0[64], cby0[64], cbx1[64], cby1[64], carea[64];
    int j0 = cb * 64;
    int j = j0 + t;
    if (j < K_PRE) {
        const float* P = &g_props[(img * K_PRE + j) * 4];
        float x1 = P[0], y1 = P[1], x2 = P[2], y2 = P[3];
        cbx0[t] = x1; cby0[t] = y1; cbx1[t] = x2; cby1[t] = y2;
        carea[t] = __fmul_rn(__fadd_rn(__fsub_rn(x2, x1), 1.0f),
                             __fadd_rn(__fsub_rn(y2, y1), 1.0f));
    }
    __syncthreads();
    unsigned long long m = 0ull;
    if (row < K_PRE) {
        const float* P = &g_props[(img * K_PRE + row) * 4];
        float x1 = P[0], y1 = P[1], x2 = P[2], y2 = P[3];
        float ai = __fmul_rn(__fadd_rn(__fsub_rn(x2, x1), 1.0f),
                             __fadd_rn(__fsub_rn(y2, y1), 1.0f));
        int lim = K_PRE - j0; if (lim > 64) lim = 64;
        for (int jj = 0; jj < lim; jj++) {
            int jg = j0 + jj;
            if (jg > row) {
                float lx = fmaxf(x1, cbx0[jj]);
                float ly = fmaxf(y1, cby0[jj]);
                float rx = fminf(x2, cbx1[jj]);
                float ry = fminf(y2, cby1[jj]);
                float iw = fmaxf(__fadd_rn(__fsub_rn(rx, lx), 1.0f), 0.0f);
                float ih = fmaxf(__fadd_rn(__fsub_rn(ry, ly), 1.0f), 0.0f);
                float inter = __fmul_rn(iw, ih);
                float den = __fsub_rn(__fadd_rn(ai, carea[jj]), inter);
                float iou = __fdiv_rn(inter, den);
                if (iou > NMS_THRESH) m |= (1ull << jj);
            }
        }
    }
    Mrow[cb] = m;
}

// ---------------- sequential greedy pass (1 block/img, warp0 consumes, 7 warps prefetch) ----------------
__global__ void greedy_kernel() {
    int img = blockIdx.x, t = threadIdx.x;   // 256 threads
    __shared__ unsigned long long buf[2][2048];   // 2 x 64 rows x 32 words
    __shared__ unsigned char sv[2048];
    __shared__ unsigned char sk[2048];
    const unsigned long long* M = &g_mask[(size_t)img * 2048 * 32];
    for (int i = t; i < 2048; i += 256) {
        sv[i] = (i < K_PRE) ? g_valid[img * K_PRE + i] : 0;
        sk[i] = 0;
        buf[0][i] = M[i];   // chunk 0 (rows 0..63)
    }
    __syncthreads();
    int wid = t >> 5, lane = t & 31;
    unsigned long long removed = 0ull;   // lane l owns removed word l (warp 0)
    for (int c = 0; c < 32; c++) {
        int cbuf = c & 1, nbuf = cbuf ^ 1;
        if (wid > 0 && (c + 1) < 32) {
            const unsigned long long* src = &M[(size_t)(c + 1) * 2048];
            for (int i = t - 32; i < 2048; i += 224) buf[nbuf][i] = src[i];
        }
        if (wid == 0) {
            unsigned long long cur = __shfl_sync(0xFFFFFFFFu, removed, c);
            int base = c * 64;
            int lim = K_PRE - base; if (lim > 64) lim = 64;
            for (int q = 0; q < lim; q++) {
                if (!((cur >> q) & 1ull) && sv[base + q]) {
                    if (lane == 0) sk[base + q] = 1;
                    removed |= buf[cbuf][q * 32 + lane];
                    cur |= buf[cbuf][q * 32 + c];
                }
            }
        }
        __syncthreads();
    }
    for (int i = t; i < K_PRE; i += 256) g_keep[img * K_PRE + i] = sk[i];
}

// ---------------- stable partition + pack output ----------------
__global__ void output_kernel(float* __restrict__ out) {
    int img = blockIdx.x, t = threadIdx.x;   // 1024 threads
    __shared__ unsigned char fl[2048];
    __shared__ int wsum[32];
    __shared__ int stot;
    for (int i = t; i < 2048; i += 1024)
        fl[i] = (i < K_PRE) ? g_keep[img * K_PRE + i] : 0;
    __syncthreads();
    int a = fl[2 * t], b = fl[2 * t + 1];
    int s = a + b;
    int lane = t & 31, wid = t >> 5;
    int v = s;
    #pragma unroll
    for (int off = 1; off < 32; off <<= 1) {
        int n = __shfl_up_sync(0xFFFFFFFFu, v, off);
        if (lane >= off) v += n;
    }
    if (lane == 31) wsum[wid] = v;
    __syncthreads();
    if (wid == 0) {
        int w = wsum[lane];
        #pragma unroll
        for (int off = 1; off < 32; off <<= 1) {
            int n = __shfl_up_sync(0xFFFFFFFFu, w, off);
            if (lane >= off) w += n;
        }
        wsum[lane] = w;
        if (lane == 31) stot = w;
    }
    __syncthreads();
    int base = (wid > 0 ? wsum[wid - 1] : 0) + (v - s);   // exclusive kept-count before 2t
    int total = stot;
    int r0 = 2 * t, r1 = 2 * t + 1;
    int e1 = base + a;
    int p0 = a ? base : total + (r0 - base);
    int p1 = b ? e1 : total + (r1 - e1);
    if (r0 < K_PRE && p0 < K_POST) {
        const float* P = &g_props[(img * K_PRE + r0) * 4];
        float* o = &out[((size_t)img * K_POST + p0) * 5];
        o[0] = P[0]; o[1] = P[1]; o[2] = P[2]; o[3] = P[3];
        o[4] = a ? g_scores[img * K_PRE + r0] : NEG_BIG;
    }
    if (r1 < K_PRE && p1 < K_POST) {
        const float* P = &g_props[(img * K_PRE + r1) * 4];
        float* o = &out[((size_t)img * K_POST + p1) * 5];
        o[0] = P[0]; o[1] = P[1]; o[2] = P[2]; o[3] = P[3];
        o[4] = b ? g_scores[img * K_PRE + r1] : NEG_BIG;
    }
}

// ---------------- launch ----------------
extern "C" void kernel_launch(void* const* d_in, const int* in_sizes, int n_in,
                              void* d_out, int out_size) {
    const float *anchors = nullptr, *obj = nullptr, *deltas = nullptr;
    for (int i = 0; i < n_in; i++) {
        if (in_sizes[i] == N_ANCH * 4)          anchors = (const float*)d_in[i];
        else if (in_sizes[i] == N_IMG * N_ANCH) obj     = (const float*)d_in[i];
        else if (in_sizes[i] == N_IMG * N_ANCH * 4) deltas = (const float*)d_in[i];
    }
    float* out = (float*)d_out;

    init_kernel<<<N_IMG, 256>>>();
    for (int pass = 0; pass < 4; pass++) {
        hist_kernel<<<dim3(64, N_IMG), 256>>>(obj, pass);
        scan_kernel<<<1, 8>>>();
    }
    compact_kernel<<<dim3(64, N_IMG), 256>>>(obj);
    sort_kernel<<<N_IMG, 1024>>>();
    decode_kernel<<<dim3(8, N_IMG), 256>>>(anchors, obj, deltas);
    mask_kernel<<<dim3(32, 32, N_IMG), 64>>>();
    greedy_kernel<<<N_IMG, 256>>>();
    output_kernel<<<N_IMG, 1024>>>(out);
    (void)out_size;
}

// round 2
// speedup vs baseline: 1.7054x; 1.7054x over previous
#include <cuda_runtime.h>
#include <cstdint>

// libdevice precise expf (what XLA lowers jnp.exp(f32) to), immune to fast-math.
extern "C" __device__ float __nv_expf(float);

// ---------------- problem constants ----------------
#define N_IMG 8
#define N_ANCH 250000
#define N_ANCH4 62500
#define K_PRE 2000
#define K_POST 1000
#define CAND_CAP 4096
#define NMS_THRESH 0.7f
#define XFORM_CLIP 4.135166556742356f
#define XMAX 1332.0f
#define YMAX 799.0f
#define NEG_BIG -1e9f
#define NBINS 4096

// ---------------- device scratch ----------------
__device__ unsigned int g_hist[N_IMG * NBINS];
__device__ unsigned int g_state[N_IMG * 4];        // [0]=threshold key, [2]=cand_cnt
__device__ unsigned long long g_cand[N_IMG * CAND_CAP];
__device__ int    g_topk_idx[N_IMG * K_PRE];
__device__ float4 g_props4[N_IMG * K_PRE];
__device__ float  g_area[N_IMG * K_PRE];
__device__ float  g_scores[N_IMG * K_PRE];
__device__ unsigned char g_valid[N_IMG * K_PRE];
__device__ unsigned long long g_mask[N_IMG * 2048 * 32];
__device__ unsigned char g_keep[N_IMG * K_PRE];

__device__ __forceinline__ unsigned int okey_of(float f) {
    unsigned int b = __float_as_uint(f);
    return b ^ ((b & 0x80000000u) ? 0xFFFFFFFFu : 0x80000000u);
}

// ---------------- init ----------------
__global__ void init_kernel() {
    int img = blockIdx.x, t = threadIdx.x;   // 8 blocks x 1024
    for (int i = t; i < NBINS; i += 1024) g_hist[img * NBINS + i] = 0u;
    if (t == 0) { g_state[img * 4 + 0] = 0u; g_state[img * 4 + 2] = 0u; }
}

// ---------------- single-pass histogram (top 12 bits of order key) ----------------
__global__ void hist_kernel(const float4* __restrict__ obj4) {
    int img = blockIdx.y;
    __shared__ unsigned int sh[2][NBINS];
    int t = threadIdx.x;
    for (int i = t; i < 2 * NBINS; i += 256) ((unsigned int*)sh)[i] = 0u;
    __syncthreads();
    int p = (t >> 5) & 1;
    const float4* o = obj4 + (size_t)img * N_ANCH4;
    for (int i = blockIdx.x * 256 + t; i < N_ANCH4; i += gridDim.x * 256) {
        float4 v = o[i];
        atomicAdd(&sh[p][okey_of(v.x) >> 20], 1u);
        atomicAdd(&sh[p][okey_of(v.y) >> 20], 1u);
        atomicAdd(&sh[p][okey_of(v.z) >> 20], 1u);
        atomicAdd(&sh[p][okey_of(v.w) >> 20], 1u);
    }
    __syncthreads();
    for (int i = t; i < NBINS; i += 256) {
        unsigned int s = sh[0][i] + sh[1][i];
        if (s) atomicAdd(&g_hist[img * NBINS + i], s);
    }
}

// ---------------- threshold scan: warp per image, descending bins ----------------
__global__ void scan_kernel() {
    int t = threadIdx.x;        // 256 = 8 warps
    int img = t >> 5, lane = t & 31;
    unsigned int cum = 0;
    for (int base = NBINS - 1; base >= 31; base -= 32) {
        int bin = base - lane;
        unsigned int c = g_hist[img * NBINS + bin];
        unsigned int v = c;
        #pragma unroll
        for (int off = 1; off < 32; off <<= 1) {
            unsigned int n = __shfl_up_sync(0xFFFFFFFFu, v, off);
            if (lane >= off) v += n;
        }
        unsigned int tot = __shfl_sync(0xFFFFFFFFu, v, 31);
        unsigned int ball = __ballot_sync(0xFFFFFFFFu, cum + v >= K_PRE);
        if (ball) {
            int l = __ffs(ball) - 1;
            if (lane == l) g_state[img * 4 + 0] = (unsigned int)bin << 20;
            break;
        }
        cum += tot;
    }
}

// ---------------- compact candidates (key >= threshold) ----------------
__global__ void compact_kernel(const float4* __restrict__ obj4) {
    int img = blockIdx.y;
    unsigned int T = g_state[img * 4 + 0];
    const float4* o = obj4 + (size_t)img * N_ANCH4;
    for (int i = blockIdx.x * 256 + threadIdx.x; i < N_ANCH4; i += gridDim.x * 256) {
        float4 v = o[i];
        #pragma unroll
        for (int c = 0; c < 4; c++) {
            float f = (c == 0) ? v.x : (c == 1) ? v.y : (c == 2) ? v.z : v.w;
            unsigned int k = okey_of(f);
            if (k >= T) {
                unsigned int pos = atomicAdd(&g_state[img * 4 + 2], 1u);
                if (pos < CAND_CAP)
                    g_cand[img * CAND_CAP + pos] =
                        ((unsigned long long)k << 32) | (unsigned int)(~(unsigned int)(4 * i + c));
            }
        }
    }
}

// ---------------- per-image bitonic sort (descending), emit top-2000 ----------------
__global__ void sort_kernel() {
    int img = blockIdx.x, t = threadIdx.x;   // 1024 threads
    __shared__ unsigned long long sh[CAND_CAP];
    unsigned int cnt = g_state[img * 4 + 2];
    if (cnt > CAND_CAP) cnt = CAND_CAP;
    for (int i = t; i < CAND_CAP; i += 1024)
        sh[i] = (i < (int)cnt) ? g_cand[img * CAND_CAP + i] : 0ull;
    __syncthreads();
    for (int k = 2; k <= CAND_CAP; k <<= 1) {
        for (int j = k >> 1; j > 0; j >>= 1) {
            for (int i = t; i < CAND_CAP; i += 1024) {
                int ixj = i ^ j;
                if (ixj > i) {
                    bool desc = ((i & k) == 0);
                    unsigned long long A = sh[i], B = sh[ixj];
                    if (desc ? (A < B) : (A > B)) { sh[i] = B; sh[ixj] = A; }
                }
            }
            __syncthreads();
        }
    }
    for (int r = t; r < K_PRE; r += 1024)
        g_topk_idx[img * K_PRE + r] = (int)(~(unsigned int)(sh[r] & 0xFFFFFFFFull));
}

// ---------------- decode + clip + valid + area + score gather ----------------
__global__ void decode_kernel(const float* __restrict__ anchors,
                              const float* __restrict__ obj,
                              const float* __restrict__ deltas) {
    int img = blockIdx.y;
    int r = blockIdx.x * blockDim.x + threadIdx.x;
    if (r >= K_PRE) return;
    int idx = g_topk_idx[img * K_PRE + r];
    const float4 A = ((const float4*)anchors)[idx];
    const float4 D = ((const float4*)deltas)[(size_t)img * N_ANCH + idx];
    float w  = __fadd_rn(__fsub_rn(A.z, A.x), 1.0f);
    float h  = __fadd_rn(__fsub_rn(A.w, A.y), 1.0f);
    float cx = __fadd_rn(A.x, __fmul_rn(0.5f, w));
    float cy = __fadd_rn(A.y, __fmul_rn(0.5f, h));
    float dw = fminf(D.z, XFORM_CLIP);
    float dh = fminf(D.w, XFORM_CLIP);
    float pcx = __fadd_rn(__fmul_rn(D.x, w), cx);
    float pcy = __fadd_rn(__fmul_rn(D.y, h), cy);
    float pw  = __fmul_rn(__nv_expf(dw), w);
    float ph  = __fmul_rn(__nv_expf(dh), h);
    float hx = __fmul_rn(0.5f, pw), hy = __fmul_rn(0.5f, ph);
    float x1 = __fsub_rn(pcx, hx);
    float y1 = __fsub_rn(pcy, hy);
    float x2 = __fsub_rn(__fadd_rn(pcx, hx), 1.0f);
    float y2 = __fsub_rn(__fadd_rn(pcy, hy), 1.0f);
    x1 = fminf(fmaxf(x1, 0.0f), XMAX);
    x2 = fminf(fmaxf(x2, 0.0f), XMAX);
    y1 = fminf(fmaxf(y1, 0.0f), YMAX);
    y2 = fminf(fmaxf(y2, 0.0f), YMAX);
    float ww = __fadd_rn(__fsub_rn(x2, x1), 1.0f);
    float hh = __fadd_rn(__fsub_rn(y2, y1), 1.0f);
    g_props4[img * K_PRE + r] = make_float4(x1, y1, x2, y2);
    g_area[img * K_PRE + r] = __fmul_rn(ww, hh);
    g_valid[img * K_PRE + r] = (ww >= 0.0f && hh >= 0.0f) ? 1 : 0;
    g_scores[img * K_PRE + r] = obj[(size_t)img * N_ANCH + idx];
}

// ---------------- 64x64 IoU bitmask (upper triangle only, div-free fast path) ----------------
__device__ __forceinline__ bool iou_sup(float4 a, float ai, float4 b, float aj) {
    float lx = fmaxf(a.x, b.x), ly = fmaxf(a.y, b.y);
    float rx = fminf(a.z, b.z), ry = fminf(a.w, b.w);
    float iw = fmaxf(__fadd_rn(__fsub_rn(rx, lx), 1.0f), 0.0f);
    float ih = fmaxf(__fadd_rn(__fsub_rn(ry, ly), 1.0f), 0.0f);
    float inter = __fmul_rn(iw, ih);
    float den = __fsub_rn(__fadd_rn(ai, aj), inter);
    float t = __fmaf_rn(-NMS_THRESH, den, inter);
    if (fabsf(t) <= __fmul_rn(1.2e-7f, den))
        return __fdiv_rn(inter, den) > NMS_THRESH;   // exact, rare
    return t > 0.0f;
}

__global__ void mask_kernel() {
    int img = blockIdx.z, rb = blockIdx.y, cb = blockIdx.x;
    if (cb < rb) return;
    __shared__ float4 cbox[64];
    __shared__ float  car[64];
    int t = threadIdx.x;   // 64 threads
    int j0 = cb * 64, j = j0 + t;
    if (j < K_PRE) {
        cbox[t] = g_props4[img * K_PRE + j];
        car[t]  = g_area[img * K_PRE + j];
    }
    __syncthreads();
    int row = rb * 64 + t;
    if (row >= K_PRE) return;
    float4 rbox = g_props4[img * K_PRE + row];
    float ai = g_area[img * K_PRE + row];
    unsigned long long m = 0ull;
    int lim = K_PRE - j0; if (lim > 64) lim = 64;
    if (cb > rb) {
        #pragma unroll 4
        for (int jj = 0; jj < lim; jj++)
            if (iou_sup(rbox, ai, cbox[jj], car[jj])) m |= (1ull << jj);
    } else {
        for (int jj = t + 1; jj < lim; jj++)
            if (iou_sup(rbox, ai, cbox[jj], car[jj])) m |= (1ull << jj);
    }
    g_mask[((size_t)img * 2048 + row) * 32 + cb] = m;
}

// ---------------- greedy pass: warp0 consumes, 7 warps prefetch, early exit ----------------
__global__ void greedy_kernel() {
    int img = blockIdx.x, t = threadIdx.x;   // 256 threads
    __shared__ unsigned long long buf[2][2048];
    __shared__ unsigned char sk[2048];
    __shared__ int done;
    const unsigned long long* M = &g_mask[(size_t)img * 2048 * 32];
    for (int i = t; i < 2048; i += 256) { sk[i] = 0; buf[0][i] = M[i]; }
    if (t == 0) done = 0;
    __syncthreads();
    int wid = t >> 5, lane = t & 31;
    unsigned long long removed = 0ull;
    if (wid == 0) {
        // fold invalid rows (and rows >= K_PRE) into removed: lane l owns rows l*64..l*64+63
        const unsigned long long* v8 = (const unsigned long long*)(g_valid + img * K_PRE);
        #pragma unroll
        for (int w = 0; w < 8; w++) {
            int wi = lane * 8 + w;
            unsigned long long x = (wi < K_PRE / 8) ? v8[wi] : 0ull;
            #pragma unroll
            for (int b = 0; b < 8; b++)
                if (!((x >> (8 * b)) & 0xFFull)) removed |= 1ull << (w * 8 + b);
        }
    }
    int nk = 0;
    for (int c = 0; c < 32; c++) {
        int cbuf = c & 1, nbuf = cbuf ^ 1;
        if (wid > 0 && (c + 1) < 32) {
            const unsigned long long* src = &M[(size_t)(c + 1) * 2048];
            for (int i = t - 32; i < 2048; i += 224) buf[nbuf][i] = src[i];
        }
        if (wid == 0) {
            unsigned long long cur = __shfl_sync(0xFFFFFFFFu, removed, c);
            int base = c * 64;
            int lim = K_PRE - base; if (lim > 64) lim = 64;
            for (int q = 0; q < lim; q++) {
                if (!((cur >> q) & 1ull)) {
                    if (lane == 0) sk[base + q] = 1;
                    removed |= buf[cbuf][q * 32 + lane];
                    cur |= buf[cbuf][q * 32 + c];
                    if (++nk >= K_POST) break;
                }
            }
            if (nk >= K_POST && lane == 0) done = 1;
        }
        __syncthreads();
        if (done) break;
    }
    for (int i = t; i < K_PRE; i += 256) g_keep[img * K_PRE + i] = sk[i];
}

// ---------------- stable partition + pack output ----------------
__global__ void output_kernel(float* __restrict__ out) {
    int img = blockIdx.x, t = threadIdx.x;   // 1024 threads
    __shared__ unsigned char fl[2048];
    __shared__ int wsum[32];
    __shared__ int stot;
    for (int i = t; i < 2048; i += 1024)
        fl[i] = (i < K_PRE) ? g_keep[img * K_PRE + i] : 0;
    __syncthreads();
    int a = fl[2 * t], b = fl[2 * t + 1];
    int s = a + b;
    int lane = t & 31, wid = t >> 5;
    int v = s;
    #pragma unroll
    for (int off = 1; off < 32; off <<= 1) {
        int n = __shfl_up_sync(0xFFFFFFFFu, v, off);
        if (lane >= off) v += n;
    }
    if (lane == 31) wsum[wid] = v;
    __syncthreads();
    if (wid == 0) {
        int w = wsum[lane];
        #pragma unroll
        for (int off = 1; off < 32; off <<= 1) {
            int n = __shfl_up_sync(0xFFFFFFFFu, w, off);
            if (lane >= off) w += n;
        }
        wsum[lane] = w;
        if (lane == 31) stot = w;
    }
    __syncthreads();
    int base = (wid > 0 ? wsum[wid - 1] : 0) + (v - s);
    int total = stot;
    int r0 = 2 * t, r1 = 2 * t + 1;
    int e1 = base + a;
    int p0 = a ? base : total + (r0 - base);
    int p1 = b ? e1 : total + (r1 - e1);
    if (r0 < K_PRE && p0 < K_POST) {
        float4 P = g_props4[img * K_PRE + r0];
        float* o = &out[((size_t)img * K_POST + p0) * 5];
        o[0] = P.x; o[1] = P.y; o[2] = P.z; o[3] = P.w;
        o[4] = a ? g_scores[img * K_PRE + r0] : NEG_BIG;
    }
    if (r1 < K_PRE && p1 < K_POST) {
        float4 P = g_props4[img * K_PRE + r1];
        float* o = &out[((size_t)img * K_POST + p1) * 5];
        o[0] = P.x; o[1] = P.y; o[2] = P.z; o[3] = P.w;
        o[4] = b ? g_scores[img * K_PRE + r1] : NEG_BIG;
    }
}

// ---------------- launch ----------------
extern "C" void kernel_launch(void* const* d_in, const int* in_sizes, int n_in,
                              void* d_out, int out_size) {
    const float *anchors = nullptr, *obj = nullptr, *deltas = nullptr;
    for (int i = 0; i < n_in; i++) {
        if (in_sizes[i] == N_ANCH * 4)              anchors = (const float*)d_in[i];
        else if (in_sizes[i] == N_IMG * N_ANCH)     obj     = (const float*)d_in[i];
        else if (in_sizes[i] == N_IMG * N_ANCH * 4) deltas  = (const float*)d_in[i];
    }
    float* out = (float*)d_out;

    init_kernel<<<N_IMG, 1024>>>();
    hist_kernel<<<dim3(128, N_IMG), 256>>>((const float4*)obj);
    scan_kernel<<<1, 256>>>();
    compact_kernel<<<dim3(128, N_IMG), 256>>>((const float4*)obj);
    sort_kernel<<<N_IMG, 1024>>>();
    decode_kernel<<<dim3(8, N_IMG), 256>>>(anchors, obj, deltas);
    mask_kernel<<<dim3(32, 32, N_IMG), 64>>>();
    greedy_kernel<<<N_IMG, 256>>>();
    output_kernel<<<N_IMG, 1024>>>(out);
    (void)out_size;
}

// round 3
// speedup vs baseline: 1.8865x; 1.1062x over previous
#include <cuda_runtime.h>
#include <cstdint>

// libdevice precise expf (what XLA lowers jnp.exp(f32) to), immune to fast-math.
extern "C" __device__ float __nv_expf(float);

// ---------------- problem constants ----------------
#define N_IMG 8
#define N_ANCH 250000
#define N_ANCH4 62500
#define K_PRE 2000
#define K_POST 1000
#define CAND_CAP 4096
#define NMS_THRESH 0.7f
#define XFORM_CLIP 4.135166556742356f
#define XMAX 1332.0f
#define YMAX 799.0f
#define NEG_BIG -1e9f
#define NBINS 4096

// ---------------- device scratch ----------------
__device__ unsigned int g_hist[N_IMG * NBINS];            // zero at load; re-zeroed by scan
__device__ unsigned int g_state[N_IMG * 4];               // [0]=threshold key, [2]=cand_cnt (reset by sortdec)
__device__ unsigned long long g_cand[N_IMG * CAND_CAP];
__device__ float4 g_props4[N_IMG * K_PRE];
__device__ float  g_area[N_IMG * K_PRE];
__device__ float  g_scores[N_IMG * K_PRE];
__device__ unsigned char g_valid[N_IMG * K_PRE];
__device__ unsigned long long g_mask[N_IMG * 2048 * 32];

__device__ __forceinline__ unsigned int okey_of(float f) {
    unsigned int b = __float_as_uint(f);
    return b ^ ((b & 0x80000000u) ? 0xFFFFFFFFu : 0x80000000u);
}

// ---------------- histogram (12-bit bins), MLP=8 tiled loads ----------------
__global__ void hist_kernel(const float4* __restrict__ obj4) {
    int img = blockIdx.y, t = threadIdx.x;
    __shared__ unsigned int sh[2][NBINS];
    for (int i = t; i < 2 * NBINS; i += 256) ((unsigned int*)sh)[i] = 0u;
    __syncthreads();
    const float4* o = obj4 + (size_t)img * N_ANCH4;
    int base = blockIdx.x * 2048 + t;
    float4 v[8]; bool m[8];
    #pragma unroll
    for (int u = 0; u < 8; u++) {
        int i = base + u * 256;
        m[u] = (i < N_ANCH4);
        v[u] = m[u] ? o[i] : make_float4(0.f, 0.f, 0.f, 0.f);
    }
    int p = (t >> 5) & 1;
    #pragma unroll
    for (int u = 0; u < 8; u++) if (m[u]) {
        atomicAdd(&sh[p][okey_of(v[u].x) >> 20], 1u);
        atomicAdd(&sh[p][okey_of(v[u].y) >> 20], 1u);
        atomicAdd(&sh[p][okey_of(v[u].z) >> 20], 1u);
        atomicAdd(&sh[p][okey_of(v[u].w) >> 20], 1u);
    }
    __syncthreads();
    for (int i = t; i < NBINS; i += 256) {
        unsigned int s = sh[0][i] + sh[1][i];
        if (s) atomicAdd(&g_hist[img * NBINS + i], s);
    }
}

// ---------------- threshold scan (warp/img) + zero hist for next replay ----------------
__global__ void scan_kernel() {
    int t = threadIdx.x, wid = t >> 5, lane = t & 31;   // 1024 threads
    if (wid < N_IMG) {
        int img = wid;
        unsigned int cum = 0;
        for (int base = NBINS - 1; base >= 31; base -= 32) {
            int bin = base - lane;
            unsigned int c = g_hist[img * NBINS + bin];
            unsigned int v = c;
            #pragma unroll
            for (int off = 1; off < 32; off <<= 1) {
                unsigned int n = __shfl_up_sync(0xFFFFFFFFu, v, off);
                if (lane >= off) v += n;
            }
            unsigned int tot = __shfl_sync(0xFFFFFFFFu, v, 31);
            unsigned int ball = __ballot_sync(0xFFFFFFFFu, cum + v >= K_PRE);
            if (ball) {
                int l = __ffs(ball) - 1;
                if (lane == l) g_state[img * 4 + 0] = (unsigned int)bin << 20;
                break;
            }
            cum += tot;
        }
    }
    __syncthreads();
    for (int i = t; i < N_IMG * NBINS; i += 1024) g_hist[i] = 0u;
}

// ---------------- compact candidates (key >= threshold), MLP=8 ----------------
__global__ void compact_kernel(const float4* __restrict__ obj4) {
    int img = blockIdx.y, t = threadIdx.x;
    unsigned int T = g_state[img * 4 + 0];
    const float4* o = obj4 + (size_t)img * N_ANCH4;
    int base = blockIdx.x * 2048 + t;
    float4 v[8]; bool m[8];
    #pragma unroll
    for (int u = 0; u < 8; u++) {
        int i = base + u * 256;
        m[u] = (i < N_ANCH4);
        v[u] = m[u] ? o[i] : make_float4(0.f, 0.f, 0.f, 0.f);
    }
    #pragma unroll
    for (int u = 0; u < 8; u++) if (m[u]) {
        int i = base + u * 256;
        #pragma unroll
        for (int c = 0; c < 4; c++) {
            float f = (c == 0) ? v[u].x : (c == 1) ? v[u].y : (c == 2) ? v[u].z : v[u].w;
            unsigned int k = okey_of(f);
            if (k >= T) {
                unsigned int pos = atomicAdd(&g_state[img * 4 + 2], 1u);
                if (pos < CAND_CAP)
                    g_cand[img * CAND_CAP + pos] =
                        ((unsigned long long)k << 32) | (unsigned int)(~(unsigned int)(4 * i + c));
            }
        }
    }
}

// ---------------- sort (refined to 2048 when possible) + fused decode ----------------
__global__ void sortdec_kernel(const float* __restrict__ anchors,
                               const float* __restrict__ deltas) {
    int img = blockIdx.x, t = threadIdx.x;   // 1024 threads
    __shared__ unsigned long long sh[CAND_CAP];       // 32 KB
    __shared__ unsigned int hist2[2048];              // 8 KB
    __shared__ unsigned int sR, sC2;
    __shared__ int c2cnt;
    unsigned int cnt = g_state[img * 4 + 2];
    if (cnt > CAND_CAP) cnt = CAND_CAP;
    for (int i = t; i < CAND_CAP; i += 1024)
        sh[i] = (i < (int)cnt) ? g_cand[img * CAND_CAP + i] : 0ull;
    int size = 2048;
    __syncthreads();
    if (cnt > 2048u) {
        for (int i = t; i < 2048; i += 1024) hist2[i] = 0u;
        __syncthreads();
        unsigned int Tq = g_state[img * 4 + 0] >> 9;
        for (int i = t; i < (int)cnt; i += 1024) {
            unsigned int k = (unsigned int)(sh[i] >> 32);
            unsigned int d = (k >> 9) - Tq; if (d > 2047u) d = 2047u;
            atomicAdd(&hist2[d], 1u);
        }
        __syncthreads();
        if (t < 32) {
            unsigned int cum = 0;
            for (int b2 = 2047; b2 >= 31; b2 -= 32) {
                int bin = b2 - t;
                unsigned int c = hist2[bin], v = c;
                #pragma unroll
                for (int off = 1; off < 32; off <<= 1) {
                    unsigned int n = __shfl_up_sync(0xFFFFFFFFu, v, off);
                    if (t >= off) v += n;
                }
                unsigned int tot = __shfl_sync(0xFFFFFFFFu, v, 31);
                unsigned int ball = __ballot_sync(0xFFFFFFFFu, cum + v >= K_PRE);
                if (ball) {
                    int l = __ffs(ball) - 1;
                    if (t == l) { sR = (unsigned int)bin; sC2 = cum + v; }
                    break;
                }
                cum += tot;
            }
            if (t == 0) c2cnt = 0;
        }
        __syncthreads();
        unsigned int R = sR, C2 = sC2;
        if (C2 <= 2048u) {
            unsigned long long mine[4]; bool q[4];
            unsigned int Tq2 = Tq;
            #pragma unroll
            for (int u = 0; u < 4; u++) {
                int i = t + u * 1024;
                mine[u] = sh[i];
                unsigned int k = (unsigned int)(mine[u] >> 32);
                unsigned int d = (k >> 9) - Tq2; if (d > 2047u) d = 2047u;
                q[u] = (i < (int)cnt) && (d >= R);
            }
            __syncthreads();
            #pragma unroll
            for (int u = 0; u < 4; u++) if (q[u]) {
                int pos = atomicAdd(&c2cnt, 1);
                sh[pos] = mine[u];
            }
            __syncthreads();
            for (int i = t; i < 2048; i += 1024) if (i >= c2cnt) sh[i] = 0ull;
            __syncthreads();
        } else {
            size = CAND_CAP;   // rare fallback: sh untouched, sort all 4096
        }
    }
    // bitonic descending over `size` (uniform per block)
    for (int k = 2; k <= size; k <<= 1) {
        for (int j = k >> 1; j > 0; j >>= 1) {
            for (int i = t; i < size; i += 1024) {
                int ixj = i ^ j;
                if (ixj > i) {
                    bool desc = ((i & k) == 0);
                    unsigned long long A = sh[i], B = sh[ixj];
                    if (desc ? (A < B) : (A > B)) { sh[i] = B; sh[ixj] = A; }
                }
            }
            __syncthreads();
        }
    }
    // fused decode of top-2000
    for (int r = t; r < K_PRE; r += 1024) {
        unsigned long long e = sh[r];
        int idx = (int)(~(unsigned int)(e & 0xFFFFFFFFull));
        unsigned int kk = (unsigned int)(e >> 32);
        float score = __uint_as_float((kk & 0x80000000u) ? (kk ^ 0x80000000u) : ~kk);
        const float4 A = ((const float4*)anchors)[idx];
        const float4 D = ((const float4*)deltas)[(size_t)img * N_ANCH + idx];
        float w  = __fadd_rn(__fsub_rn(A.z, A.x), 1.0f);
        float h  = __fadd_rn(__fsub_rn(A.w, A.y), 1.0f);
        float cx = __fadd_rn(A.x, __fmul_rn(0.5f, w));
        float cy = __fadd_rn(A.y, __fmul_rn(0.5f, h));
        float dw = fminf(D.z, XFORM_CLIP);
        float dh = fminf(D.w, XFORM_CLIP);
        float pcx = __fadd_rn(__fmul_rn(D.x, w), cx);
        float pcy = __fadd_rn(__fmul_rn(D.y, h), cy);
        float pw  = __fmul_rn(__nv_expf(dw), w);
        float ph  = __fmul_rn(__nv_expf(dh), h);
        float hx = __fmul_rn(0.5f, pw), hy = __fmul_rn(0.5f, ph);
        float x1 = __fsub_rn(pcx, hx);
        float y1 = __fsub_rn(pcy, hy);
        float x2 = __fsub_rn(__fadd_rn(pcx, hx), 1.0f);
        float y2 = __fsub_rn(__fadd_rn(pcy, hy), 1.0f);
        x1 = fminf(fmaxf(x1, 0.0f), XMAX);
        x2 = fminf(fmaxf(x2, 0.0f), XMAX);
        y1 = fminf(fmaxf(y1, 0.0f), YMAX);
        y2 = fminf(fmaxf(y2, 0.0f), YMAX);
        float ww = __fadd_rn(__fsub_rn(x2, x1), 1.0f);
        float hh = __fadd_rn(__fsub_rn(y2, y1), 1.0f);
        g_props4[img * K_PRE + r] = make_float4(x1, y1, x2, y2);
        g_area[img * K_PRE + r] = __fmul_rn(ww, hh);
        g_valid[img * K_PRE + r] = (ww >= 0.0f && hh >= 0.0f) ? 1 : 0;
        g_scores[img * K_PRE + r] = score;
    }
    if (t == 0) g_state[img * 4 + 2] = 0u;   // reset for next replay
}

// ---------------- 64x64 IoU bitmask (triangular grid, div-free fast path) ----------------
__device__ __forceinline__ bool iou_sup(float4 a, float ai, float4 b, float aj) {
    float lx = fmaxf(a.x, b.x), ly = fmaxf(a.y, b.y);
    float rx = fminf(a.z, b.z), ry = fminf(a.w, b.w);
    float iw = fmaxf(__fadd_rn(__fsub_rn(rx, lx), 1.0f), 0.0f);
    float ih = fmaxf(__fadd_rn(__fsub_rn(ry, ly), 1.0f), 0.0f);
    float inter = __fmul_rn(iw, ih);
    float den = __fsub_rn(__fadd_rn(ai, aj), inter);
    float t = __fmaf_rn(-NMS_THRESH, den, inter);
    if (fabsf(t) <= __fmul_rn(1.2e-7f, den))
        return __fdiv_rn(inter, den) > NMS_THRESH;   // exact, rare
    return t > 0.0f;
}

__global__ void mask_kernel() {
    int img = blockIdx.y;
    int u = blockIdx.x;                 // 0..527 upper-tri tiles
    int rb = 0, rem = u;
    while (rem >= 32 - rb) { rem -= 32 - rb; rb++; }
    int cb = rb + rem;
    __shared__ float4 cbox[64];
    __shared__ float  car[64];
    int t = threadIdx.x;   // 64 threads
    int j0 = cb * 64, j = j0 + t;
    if (j < K_PRE) {
        cbox[t] = g_props4[img * K_PRE + j];
        car[t]  = g_area[img * K_PRE + j];
    }
    __syncthreads();
    int row = rb * 64 + t;
    if (row >= K_PRE) return;
    float4 rbox = g_props4[img * K_PRE + row];
    float ai = g_area[img * K_PRE + row];
    unsigned long long m = 0ull;
    int lim = K_PRE - j0; if (lim > 64) lim = 64;
    if (cb > rb) {
        #pragma unroll 4
        for (int jj = 0; jj < lim; jj++)
            if (iou_sup(rbox, ai, cbox[jj], car[jj])) m |= (1ull << jj);
    } else {
        for (int jj = t + 1; jj < lim; jj++)
            if (iou_sup(rbox, ai, cbox[jj], car[jj])) m |= (1ull << jj);
    }
    g_mask[((size_t)img * 2048 + row) * 32 + cb] = m;
}

// ---------------- greedy NMS + fused stable-partition output ----------------
__global__ void greedy_kernel(float* __restrict__ out) {
    int img = blockIdx.x, t = threadIdx.x;   // 256 threads
    __shared__ unsigned long long buf[2][2048];
    __shared__ unsigned char sk[2048];
    __shared__ int done;
    __shared__ int wsum[8];
    __shared__ int stot;
    const unsigned long long* M = &g_mask[(size_t)img * 2048 * 32];
    for (int i = t; i < 2048; i += 256) { sk[i] = 0; buf[0][i] = M[i]; }
    if (t == 0) done = 0;
    __syncthreads();
    int wid = t >> 5, lane = t & 31;
    unsigned long long removed = 0ull;
    if (wid == 0) {
        const unsigned long long* v8 = (const unsigned long long*)(g_valid + img * K_PRE);
        #pragma unroll
        for (int w = 0; w < 8; w++) {
            int wi = lane * 8 + w;
            unsigned long long x = (wi < K_PRE / 8) ? v8[wi] : 0ull;
            #pragma unroll
            for (int b = 0; b < 8; b++)
                if (!((x >> (8 * b)) & 0xFFull)) removed |= 1ull << (w * 8 + b);
        }
    }
    int nk = 0;
    for (int c = 0; c < 32; c++) {
        int cbuf = c & 1, nbuf = cbuf ^ 1;
        if (wid > 0 && (c + 1) < 32) {
            const unsigned long long* src = &M[(size_t)(c + 1) * 2048];
            for (int i = t - 32; i < 2048; i += 224) buf[nbuf][i] = src[i];
        }
        if (wid == 0) {
            unsigned long long cur = __shfl_sync(0xFFFFFFFFu, removed, c);
            int base = c * 64;
            int lim = K_PRE - base; if (lim > 64) lim = 64;
            for (int q = 0; q < lim; q++) {
                if (!((cur >> q) & 1ull)) {
                    if (lane == 0) sk[base + q] = 1;
                    removed |= buf[cbuf][q * 32 + lane];
                    cur |= buf[cbuf][q * 32 + c];
                    if (++nk >= K_POST) break;
                }
            }
            if (nk >= K_POST && lane == 0) done = 1;
        }
        __syncthreads();
        if (done) break;
    }
    // ---- fused stable-partition + pack (256 threads x 8 rows) ----
    unsigned long long f8 = ((const unsigned long long*)sk)[t];
    int s = __popcll(f8);
    int v = s;
    #pragma unroll
    for (int off = 1; off < 32; off <<= 1) {
        int n = __shfl_up_sync(0xFFFFFFFFu, v, off);
        if (lane >= off) v += n;
    }
    if (lane == 31) wsum[wid] = v;
    __syncthreads();
    if (wid == 0 && lane < 8) {
        int w = wsum[lane];
        #pragma unroll
        for (int off = 1; off < 8; off <<= 1) {
            int n = __shfl_up_sync(0xFFu, w, off);
            if ((int)lane >= off) w += n;
        }
        wsum[lane] = w;
        if (lane == 7) stot = w;
    }
    __syncthreads();
    int base8 = (wid > 0 ? wsum[wid - 1] : 0) + (v - s);   // kept before row t*8
    int total = stot;
    #pragma unroll
    for (int qq = 0; qq < 8; qq++) {
        int rr = t * 8 + qq;
        if (rr >= K_PRE) break;
        int flag = (int)((f8 >> (8 * qq)) & 1ull);
        unsigned long long low = (qq == 0) ? 0ull : (f8 & ((1ull << (8 * qq)) - 1ull));
        int kb = base8 + __popcll(low);
        int p = flag ? kb : total + (rr - kb);
        if (p < K_POST) {
            float4 P = g_props4[img * K_PRE + rr];
            float* o = &out[((size_t)img * K_POST + p) * 5];
            o[0] = P.x; o[1] = P.y; o[2] = P.z; o[3] = P.w;
            o[4] = flag ? g_scores[img * K_PRE + rr] : NEG_BIG;
        }
    }
}

// ---------------- launch ----------------
extern "C" void kernel_launch(void* const* d_in, const int* in_sizes, int n_in,
                              void* d_out, int out_size) {
    const float *anchors = nullptr, *obj = nullptr, *deltas = nullptr;
    for (int i = 0; i < n_in; i++) {
        if (in_sizes[i] == N_ANCH * 4)              anchors = (const float*)d_in[i];
        else if (in_sizes[i] == N_IMG * N_ANCH)     obj     = (const float*)d_in[i];
        else if (in_sizes[i] == N_IMG * N_ANCH * 4) deltas  = (const float*)d_in[i];
    }
    float* out = (float*)d_out;

    hist_kernel<<<dim3(31, N_IMG), 256>>>((const float4*)obj);
    scan_kernel<<<1, 1024>>>();
    compact_kernel<<<dim3(31, N_IMG), 256>>>((const float4*)obj);
    sortdec_kernel<<<N_IMG, 1024>>>(anchors, deltas);
    mask_kernel<<<dim3(528, N_IMG), 64>>>();
    greedy_kernel<<<N_IMG, 256>>>(out);
    (void)out_size;
}